// round 2
// baseline (speedup 1.0000x reference)
#include <cuda_runtime.h>
#include <math.h>

#define BB 8
#define NN 10000
#define TT 2000
#define SS 12
#define HH 128

// shared-memory layout (floats)
#define SM_W1 0                    // 3*128 = 384
#define SM_B1 (SM_W1 + 3*HH)       // 128
#define SM_W2 (SM_B1 + HH)         // 128*128 = 16384
#define SM_B2 (SM_W2 + HH*HH)      // 128
#define SM_W3 (SM_B2 + HH)         // 128*12 = 1536
#define SM_B3 (SM_W3 + HH*SS)      // 12
#define SM_TOTAL (SM_B3 + SS)      // 18572 floats = 74288 bytes

// mask coefficient: GAUSS_NORM / sqrt(BIN_SIGMA) = 0.3989422804 / sqrt(0.1)
#define MASK_COEF 1.2615662610f

__global__ void zero_kernel(float* __restrict__ out, int n) {
    int i = blockIdx.x * blockDim.x + threadIdx.x;
    if (i < n) out[i] = 0.0f;
}

extern __shared__ float sm[];

__global__ __launch_bounds__(256)
void fused_sensor_kernel(
    const float* __restrict__ de,    // (B,N,3)
    const float* __restrict__ mask,  // (B,N)
    const float* __restrict__ W1,    // (3,H)
    const float* __restrict__ b1,    // (H)
    const float* __restrict__ W2,    // (H,H)
    const float* __restrict__ b2,    // (H)
    const float* __restrict__ W3,    // (H,S)
    const float* __restrict__ b3,    // (S)
    float* __restrict__ out)         // (B,S,T)
{
    // cooperative smem fill (all weights; W2 dominates at 64KB)
    for (int i = threadIdx.x; i < 3*HH;  i += blockDim.x) sm[SM_W1 + i] = W1[i];
    for (int i = threadIdx.x; i < HH;    i += blockDim.x) sm[SM_B1 + i] = b1[i];
    for (int i = threadIdx.x; i < HH*HH; i += blockDim.x) sm[SM_W2 + i] = W2[i];
    for (int i = threadIdx.x; i < HH;    i += blockDim.x) sm[SM_B2 + i] = b2[i];
    for (int i = threadIdx.x; i < HH*SS; i += blockDim.x) sm[SM_W3 + i] = W3[i];
    for (int i = threadIdx.x; i < SS;    i += blockDim.x) sm[SM_B3 + i] = b3[i];
    __syncthreads();

    int e = blockIdx.x * blockDim.x + threadIdx.x;
    if (e >= BB * NN) return;

    const float x0 = de[3*e + 0];
    const float x1 = de[3*e + 1];
    const float x2 = de[3*e + 2];

    // ---- layer 1: h1 = relu(x @ W1 + b1), h1 lives in registers ----
    float h1[HH];
#pragma unroll
    for (int h = 0; h < HH; ++h) {
        float v = fmaf(x0, sm[SM_W1 + h], sm[SM_B1 + h]);
        v = fmaf(x1, sm[SM_W1 + HH + h], v);
        v = fmaf(x2, sm[SM_W1 + 2*HH + h], v);
        h1[h] = fmaxf(v, 0.0f);
    }

    // ---- layers 2+3 fused: never materialize h2 ----
    float acc[SS];
#pragma unroll
    for (int s = 0; s < SS; ++s) acc[s] = sm[SM_B3 + s];

#pragma unroll 1
    for (int j = 0; j < HH; j += 4) {
        float4 bb4 = *(const float4*)&sm[SM_B2 + j];
        float a0 = bb4.x, a1 = bb4.y, a2 = bb4.z, a3 = bb4.w;
#pragma unroll
        for (int k = 0; k < HH; ++k) {
            float4 w = *(const float4*)&sm[SM_W2 + k*HH + j];  // broadcast LDS.128
            a0 = fmaf(h1[k], w.x, a0);
            a1 = fmaf(h1[k], w.y, a1);
            a2 = fmaf(h1[k], w.z, a2);
            a3 = fmaf(h1[k], w.w, a3);
        }
        a0 = fmaxf(a0, 0.0f);
        a1 = fmaxf(a1, 0.0f);
        a2 = fmaxf(a2, 0.0f);
        a3 = fmaxf(a3, 0.0f);
#pragma unroll
        for (int s = 0; s < SS; ++s) {
            float t = fmaf(a0, sm[SM_W3 + (j+0)*SS + s], acc[s]);
            t = fmaf(a1, sm[SM_W3 + (j+1)*SS + s], t);
            t = fmaf(a2, sm[SM_W3 + (j+2)*SS + s], t);
            acc[s] = fmaf(a3, sm[SM_W3 + (j+3)*SS + s], t);
        }
    }

    // ---- sparse Gaussian scatter ----
    // exp(-5*d^2): below 3e-20 for |d| > 3, so truncate window at +/-3 ticks.
    const float z = x2;
    const float c = mask[e] * MASK_COEF;

    int t0 = (int)ceilf(z - 3.0f);
    int t1 = (int)floorf(z + 3.0f);
    if (t0 < 0) t0 = 0;
    if (t1 > TT - 1) t1 = TT - 1;

    const int b = e / NN;
    float* ob = out + (size_t)b * SS * TT;

    for (int t = t0; t <= t1; ++t) {
        float d = (float)t - z;
        float w = __expf(-5.0f * d * d) * c;
#pragma unroll
        for (int s = 0; s < SS; ++s) {
            atomicAdd(&ob[s*TT + t], w * acc[s]);
        }
    }
}

extern "C" void kernel_launch(void* const* d_in, const int* in_sizes, int n_in,
                              void* d_out, int out_size) {
    const float* de   = (const float*)d_in[0];
    const float* mask = (const float*)d_in[1];
    const float* W1   = (const float*)d_in[2];
    const float* b1   = (const float*)d_in[3];
    const float* W2   = (const float*)d_in[4];
    const float* b2   = (const float*)d_in[5];
    const float* W3   = (const float*)d_in[6];
    const float* b3   = (const float*)d_in[7];
    float* out = (float*)d_out;

    const int total_out = BB * SS * TT;  // 192000
    zero_kernel<<<(total_out + 255) / 256, 256>>>(out, total_out);

    const int smem_bytes = SM_TOTAL * (int)sizeof(float);  // 74288 B
    cudaFuncSetAttribute(fused_sensor_kernel,
                         cudaFuncAttributeMaxDynamicSharedMemorySize, smem_bytes);

    const int threads = 256;
    const int blocks = (BB * NN + threads - 1) / threads;  // 313
    fused_sensor_kernel<<<blocks, threads, smem_bytes>>>(
        de, mask, W1, b1, W2, b2, W3, b3, out);
}